// round 1
// baseline (speedup 1.0000x reference)
#include <cuda_runtime.h>
#include <stdint.h>

#define THREADS 256
#define SPB 256         // samples per block
#define NE 30           // real experts; bin 30 = inactive/tail
#define HPAD 68         // padded h stride (68*4B=272B -> conflict-free .128 smem ops)

// ---- dynamic smem layout (in floats) ----
// sW0[384] sb0[128] sW1[8192] sb1[64] sH[256*68] sWa[2048] sba[32] sWb[64] sbb[2](+pad)
// then ints: sEid[256] sPerm[256] sCnt[31] sStart[32] sCursor[31]
#define OFF_W0   0
#define OFF_B0   384
#define OFF_W1   512
#define OFF_B1   8704
#define OFF_H    8768
#define OFF_WA   (8768 + 256*HPAD)          // 26176
#define OFF_BA   (OFF_WA + 2048)            // 28224
#define OFF_WB   (OFF_BA + 32)              // 28256
#define OFF_BB   (OFF_WB + 64)              // 28320
#define OFF_INT  (OFF_BB + 4)               // 28324 (4B-aligned words)
#define N_INTS   (256 + 256 + 31 + 32 + 31) // 606
#define SMEM_FLOATS (OFF_INT + N_INTS)
#define SMEM_BYTES  (SMEM_FLOATS * 4)

// Reciprocal without MUFU: bit-hack seed + 3 Newton steps (d > 0).
// seed err ~5% -> 2.5e-3 -> 6e-6 -> 4e-11.
__device__ __forceinline__ float fast_rcp(float d) {
    float r = __int_as_float(0x7EF311C3 - __float_as_int(d));
    r = r * (2.0f - d * r);
    r = r * (2.0f - d * r);
    r = r * (2.0f - d * r);
    return r;
}

// tanh via Pade[7/6] (continued fraction 1,3,5,7,...,13), all FMA-pipe.
// |err| <= ~2e-6 for |x|<=3, <= ~1e-4 at the +-5 clamp.
__device__ __forceinline__ float tanh_pade(float v) {
    float cx = fminf(fmaxf(v, -5.0f), 5.0f);
    float u = cx * cx;
    float p = fmaf(u, 7.3996004e-6f, 2.7972028e-3f);
    p = fmaf(u, p, 0.12820513f);
    p = fmaf(u, p, 1.0f);
    p = p * cx;
    float q = fmaf(u, 2.0718881e-4f, 0.023310023f);
    q = fmaf(u, q, 0.46153846f);
    q = fmaf(u, q, 1.0f);
    return p * fast_rcp(q);
}

extern __shared__ float smem[];

__global__ __launch_bounds__(THREADS, 1)
void wfc_fused_kernel(const float* __restrict__ x,
                      const int* __restrict__ nn,
                      const int* __restrict__ ll,
                      const int* __restrict__ mm,
                      const float* __restrict__ W0, const float* __restrict__ b0,
                      const float* __restrict__ W1, const float* __restrict__ b1,
                      const float* __restrict__ Wa, const float* __restrict__ ba,
                      const float* __restrict__ Wb, const float* __restrict__ bb,
                      float* __restrict__ out, int B)
{
    float* sW0 = smem + OFF_W0;
    float* sb0 = smem + OFF_B0;
    float* sW1 = smem + OFF_W1;
    float* sb1 = smem + OFF_B1;
    float* sH  = smem + OFF_H;
    float* sWa = smem + OFF_WA;
    float* sba = smem + OFF_BA;
    float* sWb = smem + OFF_WB;
    float* sbb = smem + OFF_BB;
    int* sEid    = (int*)(smem + OFF_INT);
    int* sPerm   = sEid + 256;
    int* sCnt    = sPerm + 256;     // 31 bins (bin 30 = inactive)
    int* sStart  = sCnt + 31;       // 32
    int* sCursor = sStart + 32;     // 31

    const int t = threadIdx.x;
    const int base = blockIdx.x * SPB;

    // ---- stage trunk weights ----
    for (int i = t; i < 384;  i += THREADS) sW0[i] = W0[i];
    for (int i = t; i < 128;  i += THREADS) sb0[i] = b0[i];
    for (int i = t; i < 2048; i += THREADS) ((float4*)sW1)[i] = ((const float4*)W1)[i];
    if (t < 64) sb1[t] = b1[t];
    if (t < 31) sCnt[t] = 0;
    __syncthreads();

    // ---- phase 1: trunk (thread per sample) ----
    const int s = base + t;
    const bool active = (s < B);
    float x0 = 0.f, x1 = 0.f, x2 = 0.f;
    int eid = NE;  // inactive bin
    if (active) {
        x0 = x[3 * s + 0];
        x1 = x[3 * s + 1];
        x2 = x[3 * s + 2];
        int n = nn[s], l = ll[s], m = mm[s];
        eid = ((n - 1) * n * (2 * n - 1)) / 6 + l * l + l + m;
    }
    sEid[t] = eid;
    atomicAdd(&sCnt[eid], 1);

    float acc[64];
    #pragma unroll
    for (int k = 0; k < 64; k++) acc[k] = sb1[k];

    #pragma unroll 4
    for (int j = 0; j < 128; j++) {
        float pre = fmaf(x0, sW0[j],
                    fmaf(x1, sW0[128 + j],
                    fmaf(x2, sW0[256 + j], sb0[j])));
        float h0 = tanh_pade(pre);
        const float4* wrow = (const float4*)(sW1 + j * 64);
        #pragma unroll
        for (int k4 = 0; k4 < 16; k4++) {
            float4 wv = wrow[k4];
            acc[4 * k4 + 0] = fmaf(h0, wv.x, acc[4 * k4 + 0]);
            acc[4 * k4 + 1] = fmaf(h0, wv.y, acc[4 * k4 + 1]);
            acc[4 * k4 + 2] = fmaf(h0, wv.z, acc[4 * k4 + 2]);
            acc[4 * k4 + 3] = fmaf(h0, wv.w, acc[4 * k4 + 3]);
        }
    }
    // h1 = tanh(acc) -> smem (STS.128, stride 272B => conflict-free)
    float* hrow_w = sH + t * HPAD;
    #pragma unroll
    for (int k4 = 0; k4 < 16; k4++) {
        float4 hv;
        hv.x = tanh_pade(acc[4 * k4 + 0]);
        hv.y = tanh_pade(acc[4 * k4 + 1]);
        hv.z = tanh_pade(acc[4 * k4 + 2]);
        hv.w = tanh_pade(acc[4 * k4 + 3]);
        ((float4*)hrow_w)[k4] = hv;
    }
    __syncthreads();

    // ---- phase 2: counting sort by expert (in-block) ----
    if (t == 0) {
        int run = 0;
        #pragma unroll
        for (int e = 0; e <= NE; e++) { sStart[e] = run; sCursor[e] = run; run += sCnt[e]; }
        sStart[NE + 1] = run;
    }
    __syncthreads();
    {
        int pos = atomicAdd(&sCursor[eid], 1);
        sPerm[pos] = t;
    }
    __syncthreads();

    // ---- phase 3: expert heads, warp-per-sample ----
    const int warp = t >> 5;
    const int lane = t & 31;

    for (int e = 0; e < NE; e++) {
        const int st = sStart[e];
        const int en = sStart[e + 1];
        const bool has = (en > st);
        if (has) {
            const float4* gWa = (const float4*)(Wa + e * 2048);
            for (int i = t; i < 512; i += THREADS) ((float4*)sWa)[i] = gWa[i];
            if (t < 32) sba[t] = ba[e * 32 + t];
            if (t < 64) sWb[t] = Wb[e * 64 + t];
            if (t < 2)  sbb[t] = bb[e * 2 + t];
        }
        __syncthreads();
        if (has) {
            for (int i = st + warp; i < en; i += 8) {
                const int sl = sPerm[i];
                const float* hrow = sH + sl * HPAD;
                float g0 = sba[lane], g1 = 0.f, g2 = 0.f, g3 = 0.f;
                #pragma unroll
                for (int j4 = 0; j4 < 16; j4++) {
                    float4 h4 = ((const float4*)hrow)[j4];  // broadcast
                    g0 = fmaf(h4.x, sWa[(4 * j4 + 0) * 32 + lane], g0);
                    g1 = fmaf(h4.y, sWa[(4 * j4 + 1) * 32 + lane], g1);
                    g2 = fmaf(h4.z, sWa[(4 * j4 + 2) * 32 + lane], g2);
                    g3 = fmaf(h4.w, sWa[(4 * j4 + 3) * 32 + lane], g3);
                }
                float g = tanh_pade((g0 + g1) + (g2 + g3));
                float p0 = g * sWb[lane * 2 + 0];
                float p1 = g * sWb[lane * 2 + 1];
                #pragma unroll
                for (int off = 16; off > 0; off >>= 1) {
                    p0 += __shfl_xor_sync(0xffffffffu, p0, off);
                    p1 += __shfl_xor_sync(0xffffffffu, p1, off);
                }
                if (lane == 0) {
                    p0 += sbb[0];
                    p1 += sbb[1];
                    float r = rsqrtf(fmaf(p0, p0, fmaf(p1, p1, 1e-6f)));
                    ((float2*)out)[base + sl] = make_float2(p0 * r, p1 * r);
                }
            }
        }
        __syncthreads();
    }
}

extern "C" void kernel_launch(void* const* d_in, const int* in_sizes, int n_in,
                              void* d_out, int out_size) {
    const float* x  = (const float*)d_in[0];
    const int*   nn = (const int*)  d_in[1];
    const int*   ll = (const int*)  d_in[2];
    const int*   mm = (const int*)  d_in[3];
    const float* W0 = (const float*)d_in[4];
    const float* b0 = (const float*)d_in[5];
    const float* W1 = (const float*)d_in[6];
    const float* b1 = (const float*)d_in[7];
    const float* Wa = (const float*)d_in[8];
    const float* ba = (const float*)d_in[9];
    const float* Wb = (const float*)d_in[10];
    const float* bb = (const float*)d_in[11];
    float* out = (float*)d_out;

    const int B = in_sizes[1];                 // n has B elements
    const int blocks = (B + SPB - 1) / SPB;

    cudaFuncSetAttribute(wfc_fused_kernel,
                         cudaFuncAttributeMaxDynamicSharedMemorySize, SMEM_BYTES);
    wfc_fused_kernel<<<blocks, THREADS, SMEM_BYTES>>>(
        x, nn, ll, mm, W0, b0, W1, b1, Wa, ba, Wb, bb, out, B);
}

// round 2
// speedup vs baseline: 1.2392x; 1.2392x over previous
#include <cuda_runtime.h>
#include <stdint.h>

#define THREADS 512
#define SPB 256         // samples per block
#define NE 30           // real experts; bin 30 = inactive/tail
#define HPAD 68         // padded h stride

typedef unsigned long long u64;

// ---- dynamic smem layout (in floats) ----
#define OFF_W0   0
#define OFF_B0   384
#define OFF_W1   512
#define OFF_B1   8704
#define OFF_H    8768
#define OFF_WA   (8768 + 256*HPAD)
#define OFF_BA   (OFF_WA + 2048)
#define OFF_WB   (OFF_BA + 32)
#define OFF_BB   (OFF_WB + 64)
#define OFF_INT  (OFF_BB + 4)
#define N_INTS   (256 + 256 + 31 + 32 + 31)
#define SMEM_FLOATS (OFF_INT + N_INTS)
#define SMEM_BYTES  (SMEM_FLOATS * 4)

// ---------- packed f32x2 helpers (sm_103a FFMA2 path) ----------
__device__ __forceinline__ u64 pk2(float lo, float hi) {
    u64 r; asm("mov.b64 %0,{%1,%2};" : "=l"(r) : "f"(lo), "f"(hi)); return r;
}
__device__ __forceinline__ void upk2(u64 v, float& lo, float& hi) {
    asm("mov.b64 {%0,%1},%2;" : "=f"(lo), "=f"(hi) : "l"(v));
}
__device__ __forceinline__ u64 fma2v(u64 a, u64 b, u64 c) {
    u64 d; asm("fma.rn.f32x2 %0,%1,%2,%3;" : "=l"(d) : "l"(a), "l"(b), "l"(c)); return d;
}
__device__ __forceinline__ void fma2acc(u64& d, u64 a, u64 b) {
    asm("fma.rn.f32x2 %0,%1,%2,%0;" : "+l"(d) : "l"(a), "l"(b));
}
__device__ __forceinline__ u64 mul2v(u64 a, u64 b) {
    u64 d; asm("mul.rn.f32x2 %0,%1,%2;" : "=l"(d) : "l"(a), "l"(b)); return d;
}

// scalar reciprocal, no MUFU (2 Newton steps: rel err ~6e-6)
__device__ __forceinline__ float fast_rcp(float d) {
    float r = __int_as_float(0x7EF311C3 - __float_as_int(d));
    r = r * (2.0f - d * r);
    r = r * (2.0f - d * r);
    return r;
}

// scalar tanh, Pade[7/6], FMA-pipe only
__device__ __forceinline__ float tanh_pade(float v) {
    float cx = fminf(fmaxf(v, -5.0f), 5.0f);
    float u = cx * cx;
    float p = fmaf(u, 7.3996004e-6f, 2.7972028e-3f);
    p = fmaf(u, p, 0.12820513f);
    p = fmaf(u, p, 1.0f);
    p = p * cx;
    float q = fmaf(u, 2.0718881e-4f, 0.023310023f);
    q = fmaf(u, q, 0.46153846f);
    q = fmaf(u, q, 1.0f);
    return p * fast_rcp(q);
}

// packed tanh for a pair, FMA-pipe only (packed Newton rcp)
__device__ __forceinline__ float2 tanh2(float a, float b) {
    a = fminf(fmaxf(a, -5.0f), 5.0f);
    b = fminf(fmaxf(b, -5.0f), 5.0f);
    u64 cc = pk2(a, b);
    u64 uu = mul2v(cc, cc);
    u64 p = fma2v(uu, pk2(7.3996004e-6f, 7.3996004e-6f), pk2(2.7972028e-3f, 2.7972028e-3f));
    p = fma2v(uu, p, pk2(0.12820513f, 0.12820513f));
    p = fma2v(uu, p, pk2(1.0f, 1.0f));
    p = mul2v(p, cc);
    u64 q = fma2v(uu, pk2(2.0718881e-4f, 2.0718881e-4f), pk2(0.023310023f, 0.023310023f));
    q = fma2v(uu, q, pk2(0.46153846f, 0.46153846f));
    q = fma2v(uu, q, pk2(1.0f, 1.0f));
    float q0, q1; upk2(q, q0, q1);
    float r0 = __int_as_float(0x7EF311C3 - __float_as_int(q0));
    float r1 = __int_as_float(0x7EF311C3 - __float_as_int(q1));
    u64 rr = pk2(r0, r1);
    u64 nq = mul2v(q, pk2(-1.0f, -1.0f));
    u64 two = pk2(2.0f, 2.0f);
    rr = mul2v(rr, fma2v(nq, rr, two));
    rr = mul2v(rr, fma2v(nq, rr, two));
    u64 res = mul2v(p, rr);
    float o0, o1; upk2(res, o0, o1);
    return make_float2(o0, o1);
}

extern __shared__ float smem[];

__global__ __launch_bounds__(THREADS, 1)
void wfc_fused_kernel(const float* __restrict__ x,
                      const int* __restrict__ nn,
                      const int* __restrict__ ll,
                      const int* __restrict__ mm,
                      const float* __restrict__ W0, const float* __restrict__ b0,
                      const float* __restrict__ W1, const float* __restrict__ b1,
                      const float* __restrict__ Wa, const float* __restrict__ ba,
                      const float* __restrict__ Wb, const float* __restrict__ bb,
                      float* __restrict__ out, int B)
{
    float* sW0 = smem + OFF_W0;
    float* sb0 = smem + OFF_B0;
    float* sW1 = smem + OFF_W1;
    float* sb1 = smem + OFF_B1;
    float* sH  = smem + OFF_H;
    float* sWa = smem + OFF_WA;
    float* sba = smem + OFF_BA;
    float* sWb = smem + OFF_WB;
    float* sbb = smem + OFF_BB;
    int* sEid    = (int*)(smem + OFF_INT);
    int* sPerm   = sEid + 256;
    int* sCnt    = sPerm + 256;
    int* sStart  = sCnt + 31;
    int* sCursor = sStart + 32;

    const int t = threadIdx.x;
    const int base = blockIdx.x * SPB;
    const int sl = t & 255;          // local sample
    const int kbase = (t >> 8) << 5; // which half of the 64 outputs

    // ---- stage trunk weights ----
    for (int i = t; i < 384;  i += THREADS) sW0[i] = W0[i];
    for (int i = t; i < 128;  i += THREADS) sb0[i] = b0[i];
    for (int i = t; i < 2048; i += THREADS) ((float4*)sW1)[i] = ((const float4*)W1)[i];
    if (t < 64) sb1[t] = b1[t];
    if (t < 31) sCnt[t] = 0;
    __syncthreads();

    // ---- phase 1: trunk; 2 threads per sample, 32 outputs each ----
    const int s = base + sl;
    const bool active = (s < B);
    float x0 = 0.f, x1 = 0.f, x2 = 0.f;
    int eid = NE;
    if (active) {
        x0 = x[3 * s + 0];
        x1 = x[3 * s + 1];
        x2 = x[3 * s + 2];
        int n = nn[s], l = ll[s], m = mm[s];
        eid = ((n - 1) * n * (2 * n - 1)) / 6 + l * l + l + m;
    }
    if (t < 256) {                    // half-0 registers the sample
        sEid[t] = eid;
        atomicAdd(&sCnt[eid], 1);
    }

    const u64 xx0 = pk2(x0, x0);
    const u64 xx1 = pk2(x1, x1);
    const u64 xx2 = pk2(x2, x2);

    u64 acc2[16];
    {
        const ulonglong2* bsrc = (const ulonglong2*)(sb1 + kbase);
        #pragma unroll
        for (int q = 0; q < 8; q++) { ulonglong2 v = bsrc[q]; acc2[2*q] = v.x; acc2[2*q+1] = v.y; }
    }

    #pragma unroll 2
    for (int j = 0; j < 128; j += 2) {
        float2 wa = *(const float2*)(sW0 + j);
        float2 wb = *(const float2*)(sW0 + 128 + j);
        float2 wc = *(const float2*)(sW0 + 256 + j);
        float2 bp = *(const float2*)(sb0 + j);
        u64 pre2 = fma2v(xx0, pk2(wa.x, wa.y),
                   fma2v(xx1, pk2(wb.x, wb.y),
                   fma2v(xx2, pk2(wc.x, wc.y), pk2(bp.x, bp.y))));
        float p0, p1; upk2(pre2, p0, p1);
        float2 h = tanh2(p0, p1);
        u64 hh0 = pk2(h.x, h.x);
        u64 hh1 = pk2(h.y, h.y);
        const ulonglong2* wr0 = (const ulonglong2*)(sW1 + j * 64 + kbase);
        const ulonglong2* wr1 = (const ulonglong2*)(sW1 + (j + 1) * 64 + kbase);
        #pragma unroll
        for (int q = 0; q < 8; q++) {
            ulonglong2 v0 = wr0[q];
            fma2acc(acc2[2*q],     hh0, v0.x);
            fma2acc(acc2[2*q + 1], hh0, v0.y);
        }
        #pragma unroll
        for (int q = 0; q < 8; q++) {
            ulonglong2 v1 = wr1[q];
            fma2acc(acc2[2*q],     hh1, v1.x);
            fma2acc(acc2[2*q + 1], hh1, v1.y);
        }
    }

    // h1 = tanh(acc) -> smem
    {
        float* hrow = sH + sl * HPAD + kbase;
        #pragma unroll
        for (int q = 0; q < 8; q++) {
            float a, b, c, d;
            upk2(acc2[2*q], a, b);
            upk2(acc2[2*q + 1], c, d);
            float2 t01 = tanh2(a, b);
            float2 t23 = tanh2(c, d);
            ((float4*)hrow)[q] = make_float4(t01.x, t01.y, t23.x, t23.y);
        }
    }
    __syncthreads();

    // ---- phase 2: counting sort by expert ----
    if (t == 0) {
        int run = 0;
        #pragma unroll
        for (int e = 0; e <= NE; e++) { sStart[e] = run; sCursor[e] = run; run += sCnt[e]; }
        sStart[NE + 1] = run;
    }
    __syncthreads();
    if (t < 256) {
        int pos = atomicAdd(&sCursor[eid], 1);
        sPerm[pos] = t;
    }
    __syncthreads();

    // ---- phase 3: expert heads, warp-per-sample (16 warps) ----
    const int warp = t >> 5;
    const int lane = t & 31;

    for (int e = 0; e < NE; e++) {
        const int st = sStart[e];
        const int en = sStart[e + 1];
        const bool has = (en > st);
        if (has) {
            const float4* gWa = (const float4*)(Wa + e * 2048);
            ((float4*)sWa)[t] = gWa[t];         // 512 float4 / 512 threads
            if (t < 32) sba[t] = ba[e * 32 + t];
            if (t < 64) sWb[t] = Wb[e * 64 + t];
            if (t < 2)  sbb[t] = bb[e * 2 + t];
        }
        __syncthreads();
        if (has) {
            for (int i = st + warp; i < en; i += 16) {
                const int sm_ = sPerm[i];
                const float* hrow = sH + sm_ * HPAD;
                float g0 = sba[lane], g1 = 0.f, g2 = 0.f, g3 = 0.f;
                #pragma unroll
                for (int j4 = 0; j4 < 16; j4++) {
                    float4 h4 = ((const float4*)hrow)[j4];  // broadcast
                    g0 = fmaf(h4.x, sWa[(4 * j4 + 0) * 32 + lane], g0);
                    g1 = fmaf(h4.y, sWa[(4 * j4 + 1) * 32 + lane], g1);
                    g2 = fmaf(h4.z, sWa[(4 * j4 + 2) * 32 + lane], g2);
                    g3 = fmaf(h4.w, sWa[(4 * j4 + 3) * 32 + lane], g3);
                }
                float g = tanh_pade((g0 + g1) + (g2 + g3));
                float p0 = g * sWb[lane * 2 + 0];
                float p1 = g * sWb[lane * 2 + 1];
                #pragma unroll
                for (int off = 16; off > 0; off >>= 1) {
                    p0 += __shfl_xor_sync(0xffffffffu, p0, off);
                    p1 += __shfl_xor_sync(0xffffffffu, p1, off);
                }
                if (lane == 0) {
                    p0 += sbb[0];
                    p1 += sbb[1];
                    float r = rsqrtf(fmaf(p0, p0, fmaf(p1, p1, 1e-6f)));
                    ((float2*)out)[base + sm_] = make_float2(p0 * r, p1 * r);
                }
            }
        }
        __syncthreads();
    }
}

extern "C" void kernel_launch(void* const* d_in, const int* in_sizes, int n_in,
                              void* d_out, int out_size) {
    const float* x  = (const float*)d_in[0];
    const int*   nn = (const int*)  d_in[1];
    const int*   ll = (const int*)  d_in[2];
    const int*   mm = (const int*)  d_in[3];
    const float* W0 = (const float*)d_in[4];
    const float* b0 = (const float*)d_in[5];
    const float* W1 = (const float*)d_in[6];
    const float* b1 = (const float*)d_in[7];
    const float* Wa = (const float*)d_in[8];
    const float* ba = (const float*)d_in[9];
    const float* Wb = (const float*)d_in[10];
    const float* bb = (const float*)d_in[11];
    float* out = (float*)d_out;

    const int B = in_sizes[1];
    const int blocks = (B + SPB - 1) / SPB;

    cudaFuncSetAttribute(wfc_fused_kernel,
                         cudaFuncAttributeMaxDynamicSharedMemorySize, SMEM_BYTES);
    wfc_fused_kernel<<<blocks, THREADS, SMEM_BYTES>>>(
        x, nn, ll, mm, W0, b0, W1, b1, Wa, ba, Wb, bb, out, B);
}

// round 3
// speedup vs baseline: 1.3181x; 1.0637x over previous
#include <cuda_runtime.h>
#include <stdint.h>

#define THREADS 512
#define SPB 256
#define NE 30
#define H0S 260          // h0T row stride (floats)
#define HPAD 68          // sH row stride
#define EBS 2176         // expert buffer stride (floats)

typedef unsigned long long u64;

// ---- smem layout (floats) ----
#define OFF_W0   0                       // 384
#define OFF_B0   384                     // 128
#define OFF_B1   512                     // 64
#define OFF_W1   576                     // 8192 -> 8768
#define OFF_H0T  8768                    // 128*260 = 33280 -> 42048 (aliased by sH: 256*68)
#define OFF_EB   42048                   // 3*2176 = 6528 -> 48576
#define OFF_INT  48576                   // ints: 256+256+31+32+31 = 606
#define SMEM_FLOATS (OFF_INT + 608)
#define SMEM_BYTES  (SMEM_FLOATS * 4)

// ---------- packed f32x2 helpers ----------
__device__ __forceinline__ u64 pk2(float lo, float hi) {
    u64 r; asm("mov.b64 %0,{%1,%2};" : "=l"(r) : "f"(lo), "f"(hi)); return r;
}
__device__ __forceinline__ void upk2(u64 v, float& lo, float& hi) {
    asm("mov.b64 {%0,%1},%2;" : "=f"(lo), "=f"(hi) : "l"(v));
}
__device__ __forceinline__ u64 fma2v(u64 a, u64 b, u64 c) {
    u64 d; asm("fma.rn.f32x2 %0,%1,%2,%3;" : "=l"(d) : "l"(a), "l"(b), "l"(c)); return d;
}
__device__ __forceinline__ void fma2acc(u64& d, u64 a, u64 b) {
    asm("fma.rn.f32x2 %0,%1,%2,%0;" : "+l"(d) : "l"(a), "l"(b));
}
__device__ __forceinline__ u64 mul2v(u64 a, u64 b) {
    u64 d; asm("mul.rn.f32x2 %0,%1,%2;" : "=l"(d) : "l"(a), "l"(b)); return d;
}

__device__ __forceinline__ float fast_rcp(float d) {
    float r = __int_as_float(0x7EF311C3 - __float_as_int(d));
    r = r * (2.0f - d * r);
    r = r * (2.0f - d * r);
    return r;
}

// scalar tanh, Pade[7/6], FMA-pipe only
__device__ __forceinline__ float tanh_pade(float v) {
    float cx = fminf(fmaxf(v, -5.0f), 5.0f);
    float u = cx * cx;
    float p = fmaf(u, 7.3996004e-6f, 2.7972028e-3f);
    p = fmaf(u, p, 0.12820513f);
    p = fmaf(u, p, 1.0f);
    p = p * cx;
    float q = fmaf(u, 2.0718881e-4f, 0.023310023f);
    q = fmaf(u, q, 0.46153846f);
    q = fmaf(u, q, 1.0f);
    return p * fast_rcp(q);
}

// packed pair tanh
__device__ __forceinline__ float2 tanh2(float a, float b) {
    a = fminf(fmaxf(a, -5.0f), 5.0f);
    b = fminf(fmaxf(b, -5.0f), 5.0f);
    u64 cc = pk2(a, b);
    u64 uu = mul2v(cc, cc);
    u64 p = fma2v(uu, pk2(7.3996004e-6f, 7.3996004e-6f), pk2(2.7972028e-3f, 2.7972028e-3f));
    p = fma2v(uu, p, pk2(0.12820513f, 0.12820513f));
    p = fma2v(uu, p, pk2(1.0f, 1.0f));
    p = mul2v(p, cc);
    u64 q = fma2v(uu, pk2(2.0718881e-4f, 2.0718881e-4f), pk2(0.023310023f, 0.023310023f));
    q = fma2v(uu, q, pk2(0.46153846f, 0.46153846f));
    q = fma2v(uu, q, pk2(1.0f, 1.0f));
    float q0, q1; upk2(q, q0, q1);
    float r0 = __int_as_float(0x7EF311C3 - __float_as_int(q0));
    float r1 = __int_as_float(0x7EF311C3 - __float_as_int(q1));
    u64 rr = pk2(r0, r1);
    u64 nq = mul2v(q, pk2(-1.0f, -1.0f));
    u64 two = pk2(2.0f, 2.0f);
    rr = mul2v(rr, fma2v(nq, rr, two));
    rr = mul2v(rr, fma2v(nq, rr, two));
    u64 res = mul2v(p, rr);
    float o0, o1; upk2(res, o0, o1);
    return make_float2(o0, o1);
}

extern __shared__ float smem[];

__global__ __launch_bounds__(THREADS, 1)
void wfc_fused_kernel(const float* __restrict__ x,
                      const int* __restrict__ nn,
                      const int* __restrict__ ll,
                      const int* __restrict__ mm,
                      const float* __restrict__ W0, const float* __restrict__ b0,
                      const float* __restrict__ W1, const float* __restrict__ b1,
                      const float* __restrict__ Wa, const float* __restrict__ ba,
                      const float* __restrict__ Wb, const float* __restrict__ bb,
                      float* __restrict__ out, int B)
{
    float* sW0  = smem + OFF_W0;
    float* sb0  = smem + OFF_B0;
    float* sb1  = smem + OFF_B1;
    float* sW1  = smem + OFF_W1;
    float* sH0T = smem + OFF_H0T;
    float* sH   = smem + OFF_H0T;   // alias (barrier-separated reuse)
    int* sEid    = (int*)(smem + OFF_INT);
    int* sPerm   = sEid + 256;
    int* sCnt    = sPerm + 256;     // 31 bins
    int* sStart  = sCnt + 31;       // 32
    int* sCursor = sStart + 32;     // 31

    const int t = threadIdx.x;
    const int base = blockIdx.x * SPB;

    // ---- stage trunk weights ----
    for (int i = t; i < 384;  i += THREADS) sW0[i] = W0[i];
    for (int i = t; i < 128;  i += THREADS) sb0[i] = b0[i];
    for (int i = t; i < 2048; i += THREADS) ((float4*)sW1)[i] = ((const float4*)W1)[i];
    if (t < 64) sb1[t] = b1[t];
    if (t < 31) sCnt[t] = 0;
    __syncthreads();                                        // bar0

    // ================= PASS A: h0 = tanh(x@W0+b0) -> h0T[j][sample] =================
    const int sa = t & 255;          // sample handled in pass A
    const int ug = (t >> 8) * 64;    // unit base (0 or 64)
    const int s = base + sa;
    const bool active = (s < B);
    float x0 = 0.f, x1 = 0.f, x2 = 0.f;
    int eid = NE;
    if (active) {
        x0 = x[3 * s + 0];
        x1 = x[3 * s + 1];
        x2 = x[3 * s + 2];
        int n = nn[s], l = ll[s], m = mm[s];
        eid = ((n - 1) * n * (2 * n - 1)) / 6 + l * l + l + m;
    }
    if (t < 256) {
        sEid[t] = eid;
        atomicAdd(&sCnt[eid], 1);
    }
    {
        const u64 xx0 = pk2(x0, x0);
        const u64 xx1 = pk2(x1, x1);
        const u64 xx2 = pk2(x2, x2);
        float* hdst = sH0T + ug * H0S + sa;
        #pragma unroll 8
        for (int up = 0; up < 32; up++) {
            const int u = ug + 2 * up;
            float2 wa2 = *(const float2*)(sW0 + u);
            float2 wb2 = *(const float2*)(sW0 + 128 + u);
            float2 wc2 = *(const float2*)(sW0 + 256 + u);
            float2 bp2 = *(const float2*)(sb0 + u);
            u64 pre = fma2v(xx0, pk2(wa2.x, wa2.y),
                      fma2v(xx1, pk2(wb2.x, wb2.y),
                      fma2v(xx2, pk2(wc2.x, wc2.y), pk2(bp2.x, bp2.y))));
            float p0, p1; upk2(pre, p0, p1);
            float2 h = tanh2(p0, p1);
            hdst[0]   = h.x;
            hdst[H0S] = h.y;
            hdst += 2 * H0S;
        }
    }
    __syncthreads();                                        // bar1

    // t0: exclusive scan of expert counts (overlapped with everyone's pass B)
    if (t == 0) {
        int run = 0;
        #pragma unroll
        for (int e = 0; e <= NE; e++) { sStart[e] = run; sCursor[e] = run; run += sCnt[e]; }
    }

    // ================= PASS B: C[256x64] = h0T @ W1, register-tiled =================
    const int sg = t & 127;          // 2 samples: 2sg, 2sg+1
    const int og = t >> 7;           // 4 output groups of 16
    const int o  = og * 16;
    u64 a0[8], a1[8];
    {
        const u64* binit = (const u64*)(sb1 + o);
        #pragma unroll
        for (int q = 0; q < 8; q++) { a0[q] = binit[q]; a1[q] = binit[q]; }
    }
    {
        const float* hptr = sH0T + 2 * sg;
        const float* wptr = sW1 + o;
        #pragma unroll 4
        for (int j = 0; j < 128; j++) {
            u64 hp = *(const u64*)hptr;
            float h0, h1; upk2(hp, h0, h1);
            u64 hh0 = pk2(h0, h0);
            u64 hh1 = pk2(h1, h1);
            const ulonglong2* wr = (const ulonglong2*)wptr;
            #pragma unroll
            for (int q = 0; q < 4; q++) {
                ulonglong2 wv = wr[q];
                fma2acc(a0[2*q],   hh0, wv.x);
                fma2acc(a0[2*q+1], hh0, wv.y);
                fma2acc(a1[2*q],   hh1, wv.x);
                fma2acc(a1[2*q+1], hh1, wv.y);
            }
            hptr += H0S;
            wptr += 64;
        }
    }
    __syncthreads();                                        // bar2 (h0T reads done)

    // scatter by expert (scan guaranteed done: t0 did it before reaching bar2)
    if (t < 256) {
        int pos = atomicAdd(&sCursor[eid], 1);
        sPerm[pos] = t;
    }
    // epilogue: tanh + write sH (overwrites h0T region — safe after bar2)
    {
        float* hr0 = sH + (2 * sg) * HPAD + o;
        float* hr1 = hr0 + HPAD;
        #pragma unroll
        for (int q = 0; q < 4; q++) {
            float v0, v1, v2, v3;
            upk2(a0[2*q], v0, v1); upk2(a0[2*q+1], v2, v3);
            float2 t01 = tanh2(v0, v1); float2 t23 = tanh2(v2, v3);
            ((float4*)hr0)[q] = make_float4(t01.x, t01.y, t23.x, t23.y);
            upk2(a1[2*q], v0, v1); upk2(a1[2*q+1], v2, v3);
            t01 = tanh2(v0, v1); t23 = tanh2(v2, v3);
            ((float4*)hr1)[q] = make_float4(t01.x, t01.y, t23.x, t23.y);
        }
    }

    // ================= PHASE 3: expert heads =================
    const int warp = t >> 5;
    const int lane = t & 31;
    const int jj = t >> 3;                 // Wa row this thread stages
    const int kb = (t & 7) * 4;            // Wa col base
    const int jh = jj >> 1, jp = jj & 1;

    // prefetch expert 0
    float4 wa_r = ((const float4*)Wa)[t];
    float ext = 0.f;
    if (t < 32)       ext = ba[t];
    else if (t < 96)  ext = Wb[t - 32];
    else if (t < 98)  ext = bb[t - 96];

    for (int e = 0; e < NE; e++) {
        float* buf = smem + OFF_EB + (e % 3) * EBS;
        // stage expert e (interleaved j-pair layout), from prefetched regs
        {
            float* wdst = buf + jh * 64 + jp;
            wdst[(kb + 0) * 2] = wa_r.x;
            wdst[(kb + 1) * 2] = wa_r.y;
            wdst[(kb + 2) * 2] = wa_r.z;
            wdst[(kb + 3) * 2] = wa_r.w;
            if (t < 32)       buf[2048 + t] = ext;
            else if (t < 96)  buf[2080 + (t - 32)] = ext;
            else if (t < 98)  buf[2144 + (t - 96)] = ext;
        }
        // prefetch expert e+1 (hidden behind bar + compute)
        if (e + 1 < NE) {
            wa_r = ((const float4*)(Wa + (e + 1) * 2048))[t];
            if (t < 32)       ext = ba[(e + 1) * 32 + t];
            else if (t < 96)  ext = Wb[(e + 1) * 64 + (t - 32)];
            else if (t < 98)  ext = bb[(e + 1) * 2 + (t - 96)];
        }
        __syncthreads();   // stage-e visible; also orders first-iter sPerm/sH writes

        const int st = sStart[e];
        const int en = sStart[e + 1];
        for (int i = st + 4 * warp; i < en; i += 64) {
            const int i1 = (i + 1 < en) ? i + 1 : i;
            const int i2 = (i + 2 < en) ? i + 2 : i;
            const int i3 = (i + 3 < en) ? i + 3 : i;
            const int p0i = sPerm[i],  p1i = sPerm[i1];
            const int p2i = sPerm[i2], p3i = sPerm[i3];
            const float* h0p = sH + p0i * HPAD;
            const float* h1p = sH + p1i * HPAD;
            const float* h2p = sH + p2i * HPAD;
            const float* h3p = sH + p3i * HPAD;
            u64 g0 = 0, g1 = 0, g2 = 0, g3 = 0;
            const float* wap = buf + lane * 2;
            #pragma unroll 8
            for (int r = 0; r < 32; r++) {
                u64 wv = *(const u64*)(wap);
                fma2acc(g0, *(const u64*)(h0p + 2*r), wv);
                fma2acc(g1, *(const u64*)(h1p + 2*r), wv);
                fma2acc(g2, *(const u64*)(h2p + 2*r), wv);
                fma2acc(g3, *(const u64*)(h3p + 2*r), wv);
                wap += 64;
            }
            const float bal = buf[2048 + lane];
            float a, b;
            upk2(g0, a, b); float G0 = (a + b) + bal;
            upk2(g1, a, b); float G1 = (a + b) + bal;
            upk2(g2, a, b); float G2 = (a + b) + bal;
            upk2(g3, a, b); float G3 = (a + b) + bal;
            float2 t01 = tanh2(G0, G1);
            float2 t23 = tanh2(G2, G3);
            const u64 wb2 = *(const u64*)(buf + 2080 + lane * 2);
            u64 pp0 = mul2v(pk2(t01.x, t01.x), wb2);
            u64 pp1 = mul2v(pk2(t01.y, t01.y), wb2);
            u64 pp2 = mul2v(pk2(t23.x, t23.x), wb2);
            u64 pp3 = mul2v(pk2(t23.y, t23.y), wb2);
            float q0a, q0b, q1a, q1b, q2a, q2b, q3a, q3b;
            upk2(pp0, q0a, q0b); upk2(pp1, q1a, q1b);
            upk2(pp2, q2a, q2b); upk2(pp3, q3a, q3b);
            #pragma unroll
            for (int off = 16; off > 0; off >>= 1) {
                q0a += __shfl_xor_sync(0xffffffffu, q0a, off);
                q0b += __shfl_xor_sync(0xffffffffu, q0b, off);
                q1a += __shfl_xor_sync(0xffffffffu, q1a, off);
                q1b += __shfl_xor_sync(0xffffffffu, q1b, off);
                q2a += __shfl_xor_sync(0xffffffffu, q2a, off);
                q2b += __shfl_xor_sync(0xffffffffu, q2b, off);
                q3a += __shfl_xor_sync(0xffffffffu, q3a, off);
                q3b += __shfl_xor_sync(0xffffffffu, q3b, off);
            }
            if (lane == 0) {
                const float bb0 = buf[2144], bb1 = buf[2145];
                float u0 = q0a + bb0, v0 = q0b + bb1;
                float u1 = q1a + bb0, v1 = q1b + bb1;
                float u2 = q2a + bb0, v2 = q2b + bb1;
                float u3 = q3a + bb0, v3 = q3b + bb1;
                float r0 = rsqrtf(fmaf(u0, u0, fmaf(v0, v0, 1e-6f)));
                float r1 = rsqrtf(fmaf(u1, u1, fmaf(v1, v1, 1e-6f)));
                float r2 = rsqrtf(fmaf(u2, u2, fmaf(v2, v2, 1e-6f)));
                float r3 = rsqrtf(fmaf(u3, u3, fmaf(v3, v3, 1e-6f)));
                ((float2*)out)[base + p0i] = make_float2(u0 * r0, v0 * r0);
                if (i + 1 < en) ((float2*)out)[base + p1i] = make_float2(u1 * r1, v1 * r1);
                if (i + 2 < en) ((float2*)out)[base + p2i] = make_float2(u2 * r2, v2 * r2);
                if (i + 3 < en) ((float2*)out)[base + p3i] = make_float2(u3 * r3, v3 * r3);
            }
        }
    }
}

extern "C" void kernel_launch(void* const* d_in, const int* in_sizes, int n_in,
                              void* d_out, int out_size) {
    const float* x  = (const float*)d_in[0];
    const int*   nn = (const int*)  d_in[1];
    const int*   ll = (const int*)  d_in[2];
    const int*   mm = (const int*)  d_in[3];
    const float* W0 = (const float*)d_in[4];
    const float* b0 = (const float*)d_in[5];
    const float* W1 = (const float*)d_in[6];
    const float* b1 = (const float*)d_in[7];
    const float* Wa = (const float*)d_in[8];
    const float* ba = (const float*)d_in[9];
    const float* Wb = (const float*)d_in[10];
    const float* bb = (const float*)d_in[11];
    float* out = (float*)d_out;

    const int B = in_sizes[1];
    const int blocks = (B + SPB - 1) / SPB;

    cudaFuncSetAttribute(wfc_fused_kernel,
                         cudaFuncAttributeMaxDynamicSharedMemorySize, SMEM_BYTES);
    wfc_fused_kernel<<<blocks, THREADS, SMEM_BYTES>>>(
        x, nn, ll, mm, W0, b0, W1, b1, Wa, ba, Wb, bb, out, B);
}